// round 1
// baseline (speedup 1.0000x reference)
#include <cuda_runtime.h>
#include <cstdint>
#include <cstddef>

// Problem constants
#define B_ 8
#define S_ 4096
#define D_ 512
static __device__ __constant__ float kEPS = 1e-6f;

// ---------------------------------------------------------------------------
// Scratch (device globals: no allocation allowed)
// ---------------------------------------------------------------------------
__device__ float g_q[(size_t)B_ * S_ * D_];
__device__ float g_k[(size_t)B_ * S_ * D_];
__device__ float g_v[(size_t)B_ * S_ * D_];
__device__ float g_a[(size_t)B_ * S_ * D_];

// ---------------------------------------------------------------------------
// f32x2 packed-math helpers (ptxas will not auto-fuse; must be inline PTX)
// ---------------------------------------------------------------------------
typedef unsigned long long u64;

__device__ __forceinline__ u64 pack2(float lo, float hi) {
    u64 r;
    asm("mov.b64 %0, {%1, %2};" : "=l"(r) : "f"(lo), "f"(hi));
    return r;
}
__device__ __forceinline__ void unpack2(u64 v, float& lo, float& hi) {
    asm("mov.b64 {%0, %1}, %2;" : "=f"(lo), "=f"(hi) : "l"(v));
}
__device__ __forceinline__ u64 fma2(u64 a, u64 b, u64 c) {
    u64 d;
    asm("fma.rn.f32x2 %0, %1, %2, %3;" : "=l"(d) : "l"(a), "l"(b), "l"(c));
    return d;
}
__device__ __forceinline__ u64 mul2(u64 a, u64 b) {
    u64 d;
    asm("mul.rn.f32x2 %0, %1, %2;" : "=l"(d) : "l"(a), "l"(b));
    return d;
}

__device__ __forceinline__ float act_apply(float x, int act) {
    if (act == 1) return fmaxf(x, 0.0f);               // relu
    if (act == 2) return 1.0f / (1.0f + __expf(-x));   // sigmoid
    return x;
}

// ---------------------------------------------------------------------------
// Projection GEMM: out[m,e] = act( sum_d X[m,d] * W[e,d] + b[e] )
//   M = B*S = 32768, N = K = 512. blockIdx.z selects projection.
//   Tile 128x128x8, 256 threads, 8x8 microtile, f32x2 over the M dimension.
// ---------------------------------------------------------------------------
__global__ void __launch_bounds__(256) proj_gemm_kernel(
    const float* __restrict__ X,
    const float* __restrict__ Wq, const float* __restrict__ bq,
    const float* __restrict__ Wk, const float* __restrict__ bk,
    const float* __restrict__ Wv, const float* __restrict__ bv,
    const float* __restrict__ Wa, const float* __restrict__ ba)
{
    const int pz = blockIdx.z;
    const float* W;
    const float* bias;
    float* out;
    int act;
    if (pz == 0)      { W = Wq; bias = bq; out = g_q; act = 1; }
    else if (pz == 1) { W = Wk; bias = bk; out = g_k; act = 1; }
    else if (pz == 2) { W = Wv; bias = bv; out = g_v; act = 0; }
    else              { W = Wa; bias = ba; out = g_a; act = 2; }

    __shared__ __align__(16) float As[8][128];  // [k][row] (transposed store)
    __shared__ __align__(16) float Bs[8][128];  // [k][col]

    const int tid = threadIdx.x;
    const int tx = tid & 15;       // 0..15 -> 8 output cols
    const int ty = tid >> 4;       // 0..15 -> 8 output rows
    const int lrow = tid >> 1;     // 0..127 load row
    const int lk = (tid & 1) * 4;  // 0 or 4

    const float* Ag = X + (size_t)blockIdx.y * 128 * D_ + (size_t)lrow * D_ + lk;
    const float* Bg = W + (size_t)blockIdx.x * 128 * D_ + (size_t)lrow * D_ + lk;

    float4 aR = *(const float4*)Ag;
    float4 bR = *(const float4*)Bg;

    u64 acc2[4][8];  // [row-pair][col], u64 0 == (0.f, 0.f)
#pragma unroll
    for (int i = 0; i < 4; ++i)
#pragma unroll
        for (int j = 0; j < 8; ++j) acc2[i][j] = 0ull;

#pragma unroll 1
    for (int kt = 0; kt < D_ / 8; ++kt) {
        As[lk + 0][lrow] = aR.x; As[lk + 1][lrow] = aR.y;
        As[lk + 2][lrow] = aR.z; As[lk + 3][lrow] = aR.w;
        Bs[lk + 0][lrow] = bR.x; Bs[lk + 1][lrow] = bR.y;
        Bs[lk + 2][lrow] = bR.z; Bs[lk + 3][lrow] = bR.w;
        __syncthreads();

        if (kt < D_ / 8 - 1) {
            aR = *(const float4*)(Ag + (kt + 1) * 8);
            bR = *(const float4*)(Bg + (kt + 1) * 8);
        }

#pragma unroll
        for (int k = 0; k < 8; ++k) {
            // A rows pair naturally into f32x2 via 16B loads.
            const ulonglong2 aLo = *(const ulonglong2*)&As[k][ty * 8];
            const ulonglong2 aHi = *(const ulonglong2*)&As[k][ty * 8 + 4];
            const float4 b0 = *(const float4*)&Bs[k][tx * 8];
            const float4 b1 = *(const float4*)&Bs[k][tx * 8 + 4];
            u64 a2[4] = {aLo.x, aLo.y, aHi.x, aHi.y};
            u64 bd[8] = {pack2(b0.x, b0.x), pack2(b0.y, b0.y),
                         pack2(b0.z, b0.z), pack2(b0.w, b0.w),
                         pack2(b1.x, b1.x), pack2(b1.y, b1.y),
                         pack2(b1.z, b1.z), pack2(b1.w, b1.w)};
#pragma unroll
            for (int i2 = 0; i2 < 4; ++i2)
#pragma unroll
                for (int j = 0; j < 8; ++j)
                    acc2[i2][j] = fma2(a2[i2], bd[j], acc2[i2][j]);
        }
        __syncthreads();
    }

    // Epilogue: bias + activation + vectorized store
    const int col0 = blockIdx.x * 128 + tx * 8;
    const int row0 = blockIdx.y * 128 + ty * 8;
    float bias8[8];
#pragma unroll
    for (int j = 0; j < 8; ++j) bias8[j] = bias[col0 + j];

#pragma unroll
    for (int i2 = 0; i2 < 4; ++i2) {
        float ra[8], rb[8];
#pragma unroll
        for (int j = 0; j < 8; ++j) {
            float lo, hi;
            unpack2(acc2[i2][j], lo, hi);
            ra[j] = act_apply(lo + bias8[j], act);
            rb[j] = act_apply(hi + bias8[j], act);
        }
        const size_t o0 = (size_t)(row0 + 2 * i2) * D_ + col0;
        *(float4*)&out[o0 + 0] = make_float4(ra[0], ra[1], ra[2], ra[3]);
        *(float4*)&out[o0 + 4] = make_float4(ra[4], ra[5], ra[6], ra[7]);
        const size_t o1 = o0 + D_;
        *(float4*)&out[o1 + 0] = make_float4(rb[0], rb[1], rb[2], rb[3]);
        *(float4*)&out[o1 + 4] = make_float4(rb[4], rb[5], rb[6], rb[7]);
    }
}

// ---------------------------------------------------------------------------
// Sequential scan.
//   Grid (16, 8): blockIdx.y = batch, blockIdx.x = 32-column j-slice.
//   256 threads = 8 warps; warp handles 4 j columns; lane holds 16 i values
//   (4 contiguous float4 chunks at i = 4*(c*32 + lane)). State s[i,j] lives
//   in registers as f32x2 pairs; q/k/a/v double-buffered through SMEM with
//   register prefetch (LDG -> compute -> STS -> bar).
// ---------------------------------------------------------------------------
__global__ void __launch_bounds__(256) scan_kernel(float* __restrict__ y)
{
    const int b = blockIdx.y;
    const int jbase = blockIdx.x * 32;
    const int tid = threadIdx.x;
    const int w = tid >> 5;
    const int l = tid & 31;
    const int jb = jbase + w * 4;

    __shared__ __align__(16) float sQ[2][512];
    __shared__ __align__(16) float sK[2][512];
    __shared__ __align__(16) float sA[2][512];
    __shared__ __align__(16) float sV[2][32];

    const float* gq = g_q + (size_t)b * S_ * D_;
    const float* gk = g_k + (size_t)b * S_ * D_;
    const float* gv = g_v + (size_t)b * S_ * D_;
    const float* ga = g_a + (size_t)b * S_ * D_;
    float* gy = y + (size_t)b * S_ * D_;

    u64 s2[4][4][2];  // [i-chunk][j][e-pair]
    u64 z2[4][2];
#pragma unroll
    for (int c = 0; c < 4; ++c) {
#pragma unroll
        for (int jj = 0; jj < 4; ++jj) { s2[c][jj][0] = 0ull; s2[c][jj][1] = 0ull; }
        z2[c][0] = 0ull; z2[c][1] = 0ull;
    }

    // Prologue: stage t=0
    if (tid < 128) {
        *(float4*)&sQ[0][tid * 4] = *(const float4*)(gq + tid * 4);
        *(float4*)&sA[0][tid * 4] = *(const float4*)(ga + tid * 4);
    } else {
        const int r = tid - 128;
        *(float4*)&sK[0][r * 4] = *(const float4*)(gk + r * 4);
        if (r < 8) *(float4*)&sV[0][r * 4] = *(const float4*)(gv + jbase + r * 4);
    }
    __syncthreads();

    int p = 0;
#pragma unroll 1
    for (int t = 0; t < S_; ++t) {
        // Prefetch t+1 into registers (latency hidden under compute)
        float4 pfA, pfB;
        const bool pf = (t + 1 < S_);
        if (pf) {
            const size_t off = (size_t)(t + 1) * D_;
            if (tid < 128) {
                pfA = *(const float4*)(gq + off + tid * 4);
                pfB = *(const float4*)(ga + off + tid * 4);
            } else {
                const int r = tid - 128;
                pfA = *(const float4*)(gk + off + r * 4);
                if (r < 8) pfB = *(const float4*)(gv + off + jbase + r * 4);
            }
        }

        // Load this step's q/k/a fragments (conflict-free LDS.128, 16B stride)
        const ulonglong2* q2p = (const ulonglong2*)&sQ[p][0];
        const ulonglong2* k2p = (const ulonglong2*)&sK[p][0];
        const ulonglong2* a2p = (const ulonglong2*)&sA[p][0];
        u64 q2[4][2], k2[4][2], a2[4][2];
#pragma unroll
        for (int c = 0; c < 4; ++c) {
            const ulonglong2 qq = q2p[c * 32 + l]; q2[c][0] = qq.x; q2[c][1] = qq.y;
            const ulonglong2 kk = k2p[c * 32 + l]; k2[c][0] = kk.x; k2[c][1] = kk.y;
            const ulonglong2 aa = a2p[c * 32 + l]; a2[c][0] = aa.x; a2[c][1] = aa.y;
        }
        u64 vd[4];
#pragma unroll
        for (int jj = 0; jj < 4; ++jj) {
            const float vv = sV[p][w * 4 + jj];
            vd[jj] = pack2(vv, vv);
        }

        // State update + numerator partials:  s = a*s + k*v ; num += q*s
        u64 num2[4] = {0ull, 0ull, 0ull, 0ull};
#pragma unroll
        for (int c = 0; c < 4; ++c)
#pragma unroll
            for (int ep = 0; ep < 2; ++ep) {
#pragma unroll
                for (int jj = 0; jj < 4; ++jj) {
                    const u64 kv = mul2(k2[c][ep], vd[jj]);
                    s2[c][jj][ep] = fma2(a2[c][ep], s2[c][jj][ep], kv);
                    num2[jj] = fma2(q2[c][ep], s2[c][jj][ep], num2[jj]);
                }
            }

        // z update + denominator partial:  z = a*z + k ; den += q*z
        u64 den2 = 0ull;
#pragma unroll
        for (int c = 0; c < 4; ++c)
#pragma unroll
            for (int ep = 0; ep < 2; ++ep) {
                z2[c][ep] = fma2(a2[c][ep], z2[c][ep], k2[c][ep]);
                den2 = fma2(q2[c][ep], z2[c][ep], den2);
            }

        // Warp reduction (5 values x 5-stage butterfly)
        float lo, hi;
        float nred[4];
#pragma unroll
        for (int jj = 0; jj < 4; ++jj) { unpack2(num2[jj], lo, hi); nred[jj] = lo + hi; }
        unpack2(den2, lo, hi);
        float den = lo + hi;
#pragma unroll
        for (int off = 16; off; off >>= 1) {
            nred[0] += __shfl_xor_sync(0xffffffffu, nred[0], off);
            nred[1] += __shfl_xor_sync(0xffffffffu, nred[1], off);
            nred[2] += __shfl_xor_sync(0xffffffffu, nred[2], off);
            nred[3] += __shfl_xor_sync(0xffffffffu, nred[3], off);
            den     += __shfl_xor_sync(0xffffffffu, den, off);
        }
        if (l == 0) {
            const float inv = 1.0f / (den + kEPS);
            *(float4*)&gy[(size_t)t * D_ + jb] =
                make_float4(nred[0] * inv, nred[1] * inv, nred[2] * inv, nred[3] * inv);
        }

        // Stage t+1 into the other buffer
        if (pf) {
            if (tid < 128) {
                *(float4*)&sQ[p ^ 1][tid * 4] = pfA;
                *(float4*)&sA[p ^ 1][tid * 4] = pfB;
            } else {
                const int r = tid - 128;
                *(float4*)&sK[p ^ 1][r * 4] = pfA;
                if (r < 8) *(float4*)&sV[p ^ 1][r * 4] = pfB;
            }
        }
        __syncthreads();
        p ^= 1;
    }
}

// ---------------------------------------------------------------------------
// Launch
// ---------------------------------------------------------------------------
extern "C" void kernel_launch(void* const* d_in, const int* in_sizes, int n_in,
                              void* d_out, int out_size)
{
    const float* x  = (const float*)d_in[0];
    const float* Wq = (const float*)d_in[1];
    const float* bq = (const float*)d_in[2];
    const float* Wk = (const float*)d_in[3];
    const float* bk = (const float*)d_in[4];
    const float* Wv = (const float*)d_in[5];
    const float* bv = (const float*)d_in[6];
    const float* Wa = (const float*)d_in[7];
    const float* ba = (const float*)d_in[8];
    float* y = (float*)d_out;

    // 4 projections fused into one grid (z = projection index)
    dim3 ggrid(D_ / 128, (B_ * S_) / 128, 4);
    proj_gemm_kernel<<<ggrid, 256>>>(x, Wq, bq, Wk, bk, Wv, bv, Wa, ba);

    // Sequential scan: 16 j-slices x 8 batches = 128 persistent CTAs
    dim3 sgrid(D_ / 32, B_);
    scan_kernel<<<sgrid, 256>>>(y);
}

// round 4
// speedup vs baseline: 1.1087x; 1.1087x over previous
#include <cuda_runtime.h>
#include <cstdint>
#include <cstddef>

// Problem constants
#define B_ 8
#define S_ 4096
#define D_ 512
#define C_ 16                 // chunk length
#define NCH_ (S_ / C_)        // 256 chunks

static __device__ __constant__ float kEPS = 1e-6f;

// ---------------------------------------------------------------------------
// Scratch (device globals: no allocation allowed)
// ---------------------------------------------------------------------------
__device__ float g_q[(size_t)B_ * S_ * D_];
__device__ float g_k[(size_t)B_ * S_ * D_];
__device__ float g_v[(size_t)B_ * S_ * D_];
__device__ float g_a[(size_t)B_ * S_ * D_];

// ---------------------------------------------------------------------------
// f32x2 packed-math helpers
// ---------------------------------------------------------------------------
typedef unsigned long long u64;

__device__ __forceinline__ u64 pack2(float lo, float hi) {
    u64 r;
    asm("mov.b64 %0, {%1, %2};" : "=l"(r) : "f"(lo), "f"(hi));
    return r;
}
__device__ __forceinline__ void unpack2(u64 v, float& lo, float& hi) {
    asm("mov.b64 {%0, %1}, %2;" : "=f"(lo), "=f"(hi) : "l"(v));
}
__device__ __forceinline__ u64 fma2(u64 a, u64 b, u64 c) {
    u64 d;
    asm("fma.rn.f32x2 %0, %1, %2, %3;" : "=l"(d) : "l"(a), "l"(b), "l"(c));
    return d;
}
__device__ __forceinline__ u64 mul2(u64 a, u64 b) {
    u64 d;
    asm("mul.rn.f32x2 %0, %1, %2;" : "=l"(d) : "l"(a), "l"(b));
    return d;
}

__device__ __forceinline__ float act_apply(float x, int act) {
    if (act == 1) return fmaxf(x, 0.0f);               // relu
    if (act == 2) return 1.0f / (1.0f + __expf(-x));   // sigmoid
    return x;
}

// ---------------------------------------------------------------------------
// Projection GEMM (unchanged from round 1): out[m,e] = act(X W^T + b)
// ---------------------------------------------------------------------------
__global__ void __launch_bounds__(256) proj_gemm_kernel(
    const float* __restrict__ X,
    const float* __restrict__ Wq, const float* __restrict__ bq,
    const float* __restrict__ Wk, const float* __restrict__ bk,
    const float* __restrict__ Wv, const float* __restrict__ bv,
    const float* __restrict__ Wa, const float* __restrict__ ba)
{
    const int pz = blockIdx.z;
    const float* W;
    const float* bias;
    float* out;
    int act;
    if (pz == 0)      { W = Wq; bias = bq; out = g_q; act = 1; }
    else if (pz == 1) { W = Wk; bias = bk; out = g_k; act = 1; }
    else if (pz == 2) { W = Wv; bias = bv; out = g_v; act = 0; }
    else              { W = Wa; bias = ba; out = g_a; act = 2; }

    __shared__ __align__(16) float As[8][128];
    __shared__ __align__(16) float Bs[8][128];

    const int tid = threadIdx.x;
    const int tx = tid & 15;
    const int ty = tid >> 4;
    const int lrow = tid >> 1;
    const int lk = (tid & 1) * 4;

    const float* Ag = X + (size_t)blockIdx.y * 128 * D_ + (size_t)lrow * D_ + lk;
    const float* Bg = W + (size_t)blockIdx.x * 128 * D_ + (size_t)lrow * D_ + lk;

    float4 aR = *(const float4*)Ag;
    float4 bR = *(const float4*)Bg;

    u64 acc2[4][8];
#pragma unroll
    for (int i = 0; i < 4; ++i)
#pragma unroll
        for (int j = 0; j < 8; ++j) acc2[i][j] = 0ull;

#pragma unroll 1
    for (int kt = 0; kt < D_ / 8; ++kt) {
        As[lk + 0][lrow] = aR.x; As[lk + 1][lrow] = aR.y;
        As[lk + 2][lrow] = aR.z; As[lk + 3][lrow] = aR.w;
        Bs[lk + 0][lrow] = bR.x; Bs[lk + 1][lrow] = bR.y;
        Bs[lk + 2][lrow] = bR.z; Bs[lk + 3][lrow] = bR.w;
        __syncthreads();

        if (kt < D_ / 8 - 1) {
            aR = *(const float4*)(Ag + (kt + 1) * 8);
            bR = *(const float4*)(Bg + (kt + 1) * 8);
        }

#pragma unroll
        for (int k = 0; k < 8; ++k) {
            const ulonglong2 aLo = *(const ulonglong2*)&As[k][ty * 8];
            const ulonglong2 aHi = *(const ulonglong2*)&As[k][ty * 8 + 4];
            const float4 b0 = *(const float4*)&Bs[k][tx * 8];
            const float4 b1 = *(const float4*)&Bs[k][tx * 8 + 4];
            u64 a2[4] = {aLo.x, aLo.y, aHi.x, aHi.y};
            u64 bd[8] = {pack2(b0.x, b0.x), pack2(b0.y, b0.y),
                         pack2(b0.z, b0.z), pack2(b0.w, b0.w),
                         pack2(b1.x, b1.x), pack2(b1.y, b1.y),
                         pack2(b1.z, b1.z), pack2(b1.w, b1.w)};
#pragma unroll
            for (int i2 = 0; i2 < 4; ++i2)
#pragma unroll
                for (int j = 0; j < 8; ++j)
                    acc2[i2][j] = fma2(a2[i2], bd[j], acc2[i2][j]);
        }
        __syncthreads();
    }

    const int col0 = blockIdx.x * 128 + tx * 8;
    const int row0 = blockIdx.y * 128 + ty * 8;
    float bias8[8];
#pragma unroll
    for (int j = 0; j < 8; ++j) bias8[j] = bias[col0 + j];

#pragma unroll
    for (int i2 = 0; i2 < 4; ++i2) {
        float ra[8], rb[8];
#pragma unroll
        for (int j = 0; j < 8; ++j) {
            float lo, hi;
            unpack2(acc2[i2][j], lo, hi);
            ra[j] = act_apply(lo + bias8[j], act);
            rb[j] = act_apply(hi + bias8[j], act);
        }
        const size_t o0 = (size_t)(row0 + 2 * i2) * D_ + col0;
        *(float4*)&out[o0 + 0] = make_float4(ra[0], ra[1], ra[2], ra[3]);
        *(float4*)&out[o0 + 4] = make_float4(ra[4], ra[5], ra[6], ra[7]);
        const size_t o1 = o0 + D_;
        *(float4*)&out[o1 + 0] = make_float4(rb[0], rb[1], rb[2], rb[3]);
        *(float4*)&out[o1 + 4] = make_float4(rb[4], rb[5], rb[6], rb[7]);
    }
}

// ---------------------------------------------------------------------------
// Chunked scan (division-free).
//   Grid (16, 8): blockIdx.y = batch, blockIdx.x = 32-column j-slice.
//   512 threads = 16 warps. Warp w owns state rows i in [w*32, w*32+32);
//   thread (w, c) holds s[i, jbase+c] for those 32 i as 16 f32x2 pairs.
//
// Per chunk (C=16 steps):
//   stage2 (thread u == state row i=u):
//     A_t  = prefix cumprod of a over the chunk
//     invA = backward recurrence from one reciprocal of A_{C-1}
//     q~_t = q_t * A_t    -> SMEM (i-pair-major, [256][16] float2, padded)
//     k~_t = k_t * invA_t -> SMEM
//     z/den: zu = z0 + sum k~ ; denp[t] = q~_t * zu  (warp-shfl reduced)
//   main: per i-pair p, serial over t:
//     su = fma2(k~, v, su); nacc[t] = fma2(q~, su, nacc[t])
//   end of chunk: su *= A_{C-1};  zreg = A_{C-1} * zu
//   reduce: num[t][c] = sum over 16 warp partials; y = num/(den+eps)
// ---------------------------------------------------------------------------

// SMEM float offsets
#define SM_QTP  0                      // 256 rows * 36 floats (16 float2 + pad)
#define SM_KTP  (SM_QTP + 256*36)
#define SM_ACP  (SM_KTP + 256*36)      // 512 floats (A_{C-1}, pair layout)
#define SM_V    (SM_ACP + 512)         // [16][32]
#define SM_PART (SM_V + 512)           // [16][32][17]
#define SM_ZP   (SM_PART + 16*32*17)   // [16][17]
#define SM_INV  (SM_ZP + 16*17)        // [16]
#define SM_FLOATS (SM_INV + 16)
#define SCAN_SMEM_BYTES (SM_FLOATS * 4)

__global__ void __launch_bounds__(512, 1) scan_chunk_kernel(float* __restrict__ y)
{
    extern __shared__ __align__(16) float sm[];
    float* sQtp = sm + SM_QTP;
    float* sKtp = sm + SM_KTP;
    float* sACp = sm + SM_ACP;
    float* sV   = sm + SM_V;
    float* sPart= sm + SM_PART;
    float* sZp  = sm + SM_ZP;
    float* sInv = sm + SM_INV;

    const int b = blockIdx.y;
    const int jbase = blockIdx.x * 32;
    const int tid = threadIdx.x;
    const int w = tid >> 5;
    const int c = tid & 31;

    const float* gq = g_q + (size_t)b * S_ * D_;
    const float* gk = g_k + (size_t)b * S_ * D_;
    const float* gv = g_v + (size_t)b * S_ * D_;
    const float* ga = g_a + (size_t)b * S_ * D_;
    float* gy = y + (size_t)b * S_ * D_;

    // Persistent state: 16 i-pairs of s[:, jbase+c], plus z[i=tid]
    u64 su[16];
#pragma unroll
    for (int pp = 0; pp < 16; ++pp) su[pp] = 0ull;
    float zreg = 0.0f;

    const int i_ = tid;           // state row owned in stage2
    const int p_ = i_ >> 1;
    const int hv_ = i_ & 1;

#pragma unroll 1
    for (int ch = 0; ch < NCH_; ++ch) {
        const int t0 = ch * C_;

        // ---------------- stage2: decay prep + z/den ----------------
        {
            float av[16], A[16], invA[16], denp[16];
#pragma unroll
            for (int t = 0; t < 16; ++t)
                av[t] = ga[(size_t)(t0 + t) * D_ + i_];
            A[0] = av[0];
#pragma unroll
            for (int t = 1; t < 16; ++t) A[t] = A[t - 1] * av[t];
            const float invAC = __frcp_rn(A[15]);
            invA[15] = invAC;
#pragma unroll
            for (int t = 15; t >= 1; --t) invA[t - 1] = invA[t] * av[t];

            float zu = zreg;
#pragma unroll
            for (int t = 0; t < 16; ++t) {
                const float qv = gq[(size_t)(t0 + t) * D_ + i_];
                const float kv = gk[(size_t)(t0 + t) * D_ + i_];
                const float qt = qv * A[t];
                const float kt = kv * invA[t];
                zu += kt;
                denp[t] = qt * zu;
                sQtp[p_ * 36 + t * 2 + hv_] = qt;
                sKtp[p_ * 36 + t * 2 + hv_] = kt;
            }
            zreg = A[15] * zu;
            sACp[p_ * 2 + hv_] = A[15];

            // den partial reduce across the warp's 32 state rows
#pragma unroll
            for (int t = 0; t < 16; ++t) {
                float v = denp[t];
#pragma unroll
                for (int off = 16; off; off >>= 1)
                    v += __shfl_xor_sync(0xffffffffu, v, off);
                if (c == 0) sZp[t * 17 + w] = v;
            }
        }

        // v slice for this chunk: threads 0..127 load [16][32]
        if (tid < 128) {
            const int tv = tid >> 3;
            const int c4 = (tid & 7) << 2;
            const float4 vv = *(const float4*)(gv + (size_t)(t0 + tv) * D_ + jbase + c4);
            *(float4*)&sV[tv * 32 + c4] = vv;
        }

        __syncthreads();   // B1: q~/k~/AC/zpart/v ready

        // ---------------- main loop: state update + numerator ----------------
#pragma unroll
        for (int th = 0; th < 2; ++th) {
            u64 vd[8];
#pragma unroll
            for (int tt = 0; tt < 8; ++tt) {
                const float vv = sV[(th * 8 + tt) * 32 + c];
                vd[tt] = pack2(vv, vv);
            }
            u64 nacc[8];
#pragma unroll
            for (int tt = 0; tt < 8; ++tt) nacc[tt] = 0ull;

#pragma unroll 4
            for (int pp = 0; pp < 16; ++pp) {
                const int p = w * 16 + pp;
                const ulonglong2* kr = (const ulonglong2*)(sKtp + p * 36 + th * 16);
                const ulonglong2* qr = (const ulonglong2*)(sQtp + p * 36 + th * 16);
                const ulonglong2 k01 = kr[0], k23 = kr[1], k45 = kr[2], k67 = kr[3];
                const ulonglong2 q01 = qr[0], q23 = qr[1], q45 = qr[2], q67 = qr[3];
                u64 s = su[pp];
                s = fma2(k01.x, vd[0], s); nacc[0] = fma2(q01.x, s, nacc[0]);
                s = fma2(k01.y, vd[1], s); nacc[1] = fma2(q01.y, s, nacc[1]);
                s = fma2(k23.x, vd[2], s); nacc[2] = fma2(q23.x, s, nacc[2]);
                s = fma2(k23.y, vd[3], s); nacc[3] = fma2(q23.y, s, nacc[3]);
                s = fma2(k45.x, vd[4], s); nacc[4] = fma2(q45.x, s, nacc[4]);
                s = fma2(k45.y, vd[5], s); nacc[5] = fma2(q45.y, s, nacc[5]);
                s = fma2(k67.x, vd[6], s); nacc[6] = fma2(q67.x, s, nacc[6]);
                s = fma2(k67.y, vd[7], s); nacc[7] = fma2(q67.y, s, nacc[7]);
                su[pp] = s;
            }

            // write numerator partials: part[t][c][w]
#pragma unroll
            for (int tt = 0; tt < 8; ++tt) {
                float lo, hi;
                unpack2(nacc[tt], lo, hi);
                sPart[((th * 8 + tt) * 32 + c) * 17 + w] = lo + hi;
            }
        }

        // end-of-chunk state scale: s *= A_{C-1}
#pragma unroll
        for (int pp = 0; pp < 16; ++pp) {
            const u64 acp = *(const u64*)(sACp + (w * 16 + pp) * 2);
            su[pp] = mul2(su[pp], acp);
        }

        // den totals + inverse (16 threads)
        if (tid < 16) {
            float den = 0.0f;
#pragma unroll
            for (int ww = 0; ww < 16; ++ww) den += sZp[tid * 17 + ww];
            sInv[tid] = 1.0f / (den + kEPS);
        }

        __syncthreads();   // B2: part + inv ready

        // ---------------- reduce + output ----------------
        {
            const int t = w;        // warp w handles output row t0+w
            float num = 0.0f;
#pragma unroll
            for (int ww = 0; ww < 16; ++ww)
                num += sPart[(t * 32 + c) * 17 + ww];
            gy[(size_t)(t0 + t) * D_ + jbase + c] = num * sInv[t];
        }
        // no barrier needed here: next chunk's writes to qtp/ktp/zp/V are
        // ordered by B1'; part/inv rewrites are ordered by B1' + main phase.
    }
}

// ---------------------------------------------------------------------------
// Launch
// ---------------------------------------------------------------------------
extern "C" void kernel_launch(void* const* d_in, const int* in_sizes, int n_in,
                              void* d_out, int out_size)
{
    const float* x  = (const float*)d_in[0];
    const float* Wq = (const float*)d_in[1];
    const float* bq = (const float*)d_in[2];
    const float* Wk = (const float*)d_in[3];
    const float* bk = (const float*)d_in[4];
    const float* Wv = (const float*)d_in[5];
    const float* bv = (const float*)d_in[6];
    const float* Wa = (const float*)d_in[7];
    const float* ba = (const float*)d_in[8];
    float* y = (float*)d_out;

    // 4 projections fused into one grid (z = projection index)
    dim3 ggrid(D_ / 128, (B_ * S_) / 128, 4);
    proj_gemm_kernel<<<ggrid, 256>>>(x, Wq, bq, Wk, bk, Wv, bv, Wa, ba);

    // Chunked scan: 16 j-slices x 8 batches = 128 CTAs, 512 threads
    cudaFuncSetAttribute(scan_chunk_kernel,
                         cudaFuncAttributeMaxDynamicSharedMemorySize,
                         SCAN_SMEM_BYTES);
    dim3 sgrid(D_ / 32, B_);
    scan_chunk_kernel<<<sgrid, 512, SCAN_SMEM_BYTES>>>(y);
}

// round 5
// speedup vs baseline: 1.1255x; 1.0151x over previous
#include <cuda_runtime.h>
#include <cstdint>
#include <cstddef>

// Problem constants
#define B_ 8
#define S_ 4096
#define D_ 512
#define C_ 16                 // chunk length
#define NCH_ (S_ / C_)        // 256 chunks

static __device__ __constant__ float kEPS = 1e-6f;

// ---------------------------------------------------------------------------
// Scratch (device globals: no allocation allowed)
// ---------------------------------------------------------------------------
__device__ float g_q[(size_t)B_ * S_ * D_];
__device__ float g_k[(size_t)B_ * S_ * D_];
__device__ float g_v[(size_t)B_ * S_ * D_];
__device__ float g_a[(size_t)B_ * S_ * D_];

// ---------------------------------------------------------------------------
// f32x2 packed-math helpers
// ---------------------------------------------------------------------------
typedef unsigned long long u64;

__device__ __forceinline__ u64 pack2(float lo, float hi) {
    u64 r;
    asm("mov.b64 %0, {%1, %2};" : "=l"(r) : "f"(lo), "f"(hi));
    return r;
}
__device__ __forceinline__ void unpack2(u64 v, float& lo, float& hi) {
    asm("mov.b64 {%0, %1}, %2;" : "=f"(lo), "=f"(hi) : "l"(v));
}
__device__ __forceinline__ u64 fma2(u64 a, u64 b, u64 c) {
    u64 d;
    asm("fma.rn.f32x2 %0, %1, %2, %3;" : "=l"(d) : "l"(a), "l"(b), "l"(c));
    return d;
}
__device__ __forceinline__ u64 mul2(u64 a, u64 b) {
    u64 d;
    asm("mul.rn.f32x2 %0, %1, %2;" : "=l"(d) : "l"(a), "l"(b));
    return d;
}

__device__ __forceinline__ float act_apply(float x, int act) {
    if (act == 1) return fmaxf(x, 0.0f);               // relu
    if (act == 2) return 1.0f / (1.0f + __expf(-x));   // sigmoid
    return x;
}

// ---------------------------------------------------------------------------
// Projection GEMM (unchanged): out[m,e] = act(X W^T + b)
// ---------------------------------------------------------------------------
__global__ void __launch_bounds__(256) proj_gemm_kernel(
    const float* __restrict__ X,
    const float* __restrict__ Wq, const float* __restrict__ bq,
    const float* __restrict__ Wk, const float* __restrict__ bk,
    const float* __restrict__ Wv, const float* __restrict__ bv,
    const float* __restrict__ Wa, const float* __restrict__ ba)
{
    const int pz = blockIdx.z;
    const float* W;
    const float* bias;
    float* out;
    int act;
    if (pz == 0)      { W = Wq; bias = bq; out = g_q; act = 1; }
    else if (pz == 1) { W = Wk; bias = bk; out = g_k; act = 1; }
    else if (pz == 2) { W = Wv; bias = bv; out = g_v; act = 0; }
    else              { W = Wa; bias = ba; out = g_a; act = 2; }

    __shared__ __align__(16) float As[8][128];
    __shared__ __align__(16) float Bs[8][128];

    const int tid = threadIdx.x;
    const int tx = tid & 15;
    const int ty = tid >> 4;
    const int lrow = tid >> 1;
    const int lk = (tid & 1) * 4;

    const float* Ag = X + (size_t)blockIdx.y * 128 * D_ + (size_t)lrow * D_ + lk;
    const float* Bg = W + (size_t)blockIdx.x * 128 * D_ + (size_t)lrow * D_ + lk;

    float4 aR = *(const float4*)Ag;
    float4 bR = *(const float4*)Bg;

    u64 acc2[4][8];
#pragma unroll
    for (int i = 0; i < 4; ++i)
#pragma unroll
        for (int j = 0; j < 8; ++j) acc2[i][j] = 0ull;

#pragma unroll 1
    for (int kt = 0; kt < D_ / 8; ++kt) {
        As[lk + 0][lrow] = aR.x; As[lk + 1][lrow] = aR.y;
        As[lk + 2][lrow] = aR.z; As[lk + 3][lrow] = aR.w;
        Bs[lk + 0][lrow] = bR.x; Bs[lk + 1][lrow] = bR.y;
        Bs[lk + 2][lrow] = bR.z; Bs[lk + 3][lrow] = bR.w;
        __syncthreads();

        if (kt < D_ / 8 - 1) {
            aR = *(const float4*)(Ag + (kt + 1) * 8);
            bR = *(const float4*)(Bg + (kt + 1) * 8);
        }

#pragma unroll
        for (int k = 0; k < 8; ++k) {
            const ulonglong2 aLo = *(const ulonglong2*)&As[k][ty * 8];
            const ulonglong2 aHi = *(const ulonglong2*)&As[k][ty * 8 + 4];
            const float4 b0 = *(const float4*)&Bs[k][tx * 8];
            const float4 b1 = *(const float4*)&Bs[k][tx * 8 + 4];
            u64 a2[4] = {aLo.x, aLo.y, aHi.x, aHi.y};
            u64 bd[8] = {pack2(b0.x, b0.x), pack2(b0.y, b0.y),
                         pack2(b0.z, b0.z), pack2(b0.w, b0.w),
                         pack2(b1.x, b1.x), pack2(b1.y, b1.y),
                         pack2(b1.z, b1.z), pack2(b1.w, b1.w)};
#pragma unroll
            for (int i2 = 0; i2 < 4; ++i2)
#pragma unroll
                for (int j = 0; j < 8; ++j)
                    acc2[i2][j] = fma2(a2[i2], bd[j], acc2[i2][j]);
        }
        __syncthreads();
    }

    const int col0 = blockIdx.x * 128 + tx * 8;
    const int row0 = blockIdx.y * 128 + ty * 8;
    float bias8[8];
#pragma unroll
    for (int j = 0; j < 8; ++j) bias8[j] = bias[col0 + j];

#pragma unroll
    for (int i2 = 0; i2 < 4; ++i2) {
        float ra[8], rb[8];
#pragma unroll
        for (int j = 0; j < 8; ++j) {
            float lo, hi;
            unpack2(acc2[i2][j], lo, hi);
            ra[j] = act_apply(lo + bias8[j], act);
            rb[j] = act_apply(hi + bias8[j], act);
        }
        const size_t o0 = (size_t)(row0 + 2 * i2) * D_ + col0;
        *(float4*)&out[o0 + 0] = make_float4(ra[0], ra[1], ra[2], ra[3]);
        *(float4*)&out[o0 + 4] = make_float4(ra[4], ra[5], ra[6], ra[7]);
        const size_t o1 = o0 + D_;
        *(float4*)&out[o1 + 0] = make_float4(rb[0], rb[1], rb[2], rb[3]);
        *(float4*)&out[o1 + 4] = make_float4(rb[4], rb[5], rb[6], rb[7]);
    }
}

// ---------------------------------------------------------------------------
// Chunked scan v3 (division-free, shfl-free stage2, L2-prefetched).
//   Grid (16, 8): blockIdx.y = batch, blockIdx.x = 32-column j-slice.
//   512 threads = 16 warps. Warp w owns state rows i in [w*32, w*32+32);
//   lane c holds s[i, jbase+c] for those 32 i as 16 f32x2 pairs.
//
// Per chunk (C=16):
//   B0 (protects sDen/sACp/sV from previous chunk's readers)
//   stage2 (thread u == state row i=u):
//     A_t = prefix cumprod(a); invA via one reciprocal; q~ = q*A, k~ = k/A
//     z recurrence; per-t raw den partials -> sDen[i*17+t] (no shfl)
//   B1
//   main: L2-prefetch next chunk's q/k/a/v; then per i-pair serial over t:
//     su = fma2(k~, v, su); nacc[t] = fma2(q~, su, nacc[t]) -> sPart
//   su *= A_{C-1}
//   B2
//   output: warp w = row t0+w; num = sum_w sPart; den = sum_i sDen (LDS +
//     butterfly); y = num/(den+eps)
// ---------------------------------------------------------------------------

// SMEM float offsets
#define SM_QTP  0                      // [256][36]  (16 t * 2 hv + pad)
#define SM_KTP  (SM_QTP + 256*36)
#define SM_ACP  (SM_KTP + 256*36)      // [512] A_{C-1} in pair layout
#define SM_V    (SM_ACP + 512)         // [16][32]
#define SM_PART (SM_V + 512)           // [16][32][17] num partials
#define SM_DEN  (SM_PART + 16*32*17)   // [512][17]   raw den partials
#define SM_FLOATS (SM_DEN + 512*17)
#define SCAN_SMEM_BYTES (SM_FLOATS * 4)

__global__ void __launch_bounds__(512, 1) scan_chunk_kernel(float* __restrict__ y)
{
    extern __shared__ __align__(16) float sm[];
    float* sQtp = sm + SM_QTP;
    float* sKtp = sm + SM_KTP;
    float* sACp = sm + SM_ACP;
    float* sV   = sm + SM_V;
    float* sPart= sm + SM_PART;
    float* sDen = sm + SM_DEN;

    const int b = blockIdx.y;
    const int jbase = blockIdx.x * 32;
    const int tid = threadIdx.x;
    const int w = tid >> 5;
    const int c = tid & 31;

    const float* gq = g_q + (size_t)b * S_ * D_;
    const float* gk = g_k + (size_t)b * S_ * D_;
    const float* gv = g_v + (size_t)b * S_ * D_;
    const float* ga = g_a + (size_t)b * S_ * D_;
    float* gy = y + (size_t)b * S_ * D_;

    u64 su[16];
#pragma unroll
    for (int pp = 0; pp < 16; ++pp) su[pp] = 0ull;
    float zreg = 0.0f;

    const int i_ = tid;
    const int p_ = i_ >> 1;
    const int hv_ = i_ & 1;

    // Warm L2 for chunk 0
    {
        const int tpf = c & 15;
        const size_t roff = (size_t)tpf * D_ + w * 32;
        if (c < 16) {
            asm volatile("prefetch.global.L2 [%0];" :: "l"(gq + roff));
            asm volatile("prefetch.global.L2 [%0];" :: "l"(ga + roff));
        } else {
            asm volatile("prefetch.global.L2 [%0];" :: "l"(gk + roff));
            if (w == 0)
                asm volatile("prefetch.global.L2 [%0];"
                             :: "l"(gv + (size_t)tpf * D_ + jbase));
        }
    }

#pragma unroll 1
    for (int ch = 0; ch < NCH_; ++ch) {
        const int t0 = ch * C_;

        __syncthreads();   // B0: prev chunk's output-phase reads done

        // ---------------- stage2 ----------------
        {
            float av[16], qv[16], kv[16];
#pragma unroll
            for (int t = 0; t < 16; ++t) av[t] = ga[(size_t)(t0 + t) * D_ + i_];
#pragma unroll
            for (int t = 0; t < 16; ++t) qv[t] = gq[(size_t)(t0 + t) * D_ + i_];
#pragma unroll
            for (int t = 0; t < 16; ++t) kv[t] = gk[(size_t)(t0 + t) * D_ + i_];

            float A[16], invA[16];
            A[0] = av[0];
#pragma unroll
            for (int t = 1; t < 16; ++t) A[t] = A[t - 1] * av[t];
            invA[15] = __frcp_rn(A[15]);
#pragma unroll
            for (int t = 15; t >= 1; --t) invA[t - 1] = invA[t] * av[t];

            float zu = zreg;
#pragma unroll
            for (int t = 0; t < 16; ++t) {
                const float qt = qv[t] * A[t];
                const float kt = kv[t] * invA[t];
                zu += kt;
                sDen[i_ * 17 + t] = qt * zu;
                sQtp[p_ * 36 + t * 2 + hv_] = qt;
                sKtp[p_ * 36 + t * 2 + hv_] = kt;
            }
            zreg = A[15] * zu;
            sACp[p_ * 2 + hv_] = A[15];
        }

        // v slice for this chunk
        if (tid < 128) {
            const int tv = tid >> 3;
            const int c4 = (tid & 7) << 2;
            const float4 vv = *(const float4*)(gv + (size_t)(t0 + tv) * D_ + jbase + c4);
            *(float4*)&sV[tv * 32 + c4] = vv;
        }

        __syncthreads();   // B1: q~/k~/AC/den/v ready

        // L2 prefetch for chunk+1 (register-free; 1-2 per lane)
        if (ch + 1 < NCH_) {
            const int tpf = c & 15;
            const size_t roff = (size_t)(t0 + 16 + tpf) * D_ + w * 32;
            if (c < 16) {
                asm volatile("prefetch.global.L2 [%0];" :: "l"(gq + roff));
                asm volatile("prefetch.global.L2 [%0];" :: "l"(ga + roff));
            } else {
                asm volatile("prefetch.global.L2 [%0];" :: "l"(gk + roff));
                if (w == 0)
                    asm volatile("prefetch.global.L2 [%0];"
                                 :: "l"(gv + (size_t)(t0 + 16 + tpf) * D_ + jbase));
            }
        }

        // ---------------- main loop ----------------
#pragma unroll
        for (int th = 0; th < 2; ++th) {
            u64 vd[8];
#pragma unroll
            for (int tt = 0; tt < 8; ++tt) {
                const float vv = sV[(th * 8 + tt) * 32 + c];
                vd[tt] = pack2(vv, vv);
            }
            u64 nacc[8];
#pragma unroll
            for (int tt = 0; tt < 8; ++tt) nacc[tt] = 0ull;

#pragma unroll 4
            for (int pp = 0; pp < 16; ++pp) {
                const int p = w * 16 + pp;
                const ulonglong2* kr = (const ulonglong2*)(sKtp + p * 36 + th * 16);
                const ulonglong2* qr = (const ulonglong2*)(sQtp + p * 36 + th * 16);
                const ulonglong2 k01 = kr[0], k23 = kr[1], k45 = kr[2], k67 = kr[3];
                const ulonglong2 q01 = qr[0], q23 = qr[1], q45 = qr[2], q67 = qr[3];
                u64 s = su[pp];
                s = fma2(k01.x, vd[0], s); nacc[0] = fma2(q01.x, s, nacc[0]);
                s = fma2(k01.y, vd[1], s); nacc[1] = fma2(q01.y, s, nacc[1]);
                s = fma2(k23.x, vd[2], s); nacc[2] = fma2(q23.x, s, nacc[2]);
                s = fma2(k23.y, vd[3], s); nacc[3] = fma2(q23.y, s, nacc[3]);
                s = fma2(k45.x, vd[4], s); nacc[4] = fma2(q45.x, s, nacc[4]);
                s = fma2(k45.y, vd[5], s); nacc[5] = fma2(q45.y, s, nacc[5]);
                s = fma2(k67.x, vd[6], s); nacc[6] = fma2(q67.x, s, nacc[6]);
                s = fma2(k67.y, vd[7], s); nacc[7] = fma2(q67.y, s, nacc[7]);
                su[pp] = s;
            }

#pragma unroll
            for (int tt = 0; tt < 8; ++tt) {
                float lo, hi;
                unpack2(nacc[tt], lo, hi);
                sPart[((th * 8 + tt) * 32 + c) * 17 + w] = lo + hi;
            }
        }

        // end-of-chunk state scale: s *= A_{C-1}
#pragma unroll
        for (int pp = 0; pp < 16; ++pp) {
            const u64 acp = *(const u64*)(sACp + (w * 16 + pp) * 2);
            su[pp] = mul2(su[pp], acp);
        }

        __syncthreads();   // B2: part ready

        // ---------------- reduce + output ----------------
        {
            const int t = w;        // warp w handles output row t0+w
            float num = 0.0f;
            float dpart = 0.0f;
#pragma unroll
            for (int ww = 0; ww < 16; ++ww) {
                num   += sPart[(t * 32 + c) * 17 + ww];
                dpart += sDen[(ww * 32 + c) * 17 + t];
            }
#pragma unroll
            for (int off = 16; off; off >>= 1)
                dpart += __shfl_xor_sync(0xffffffffu, dpart, off);
            const float inv = 1.0f / (dpart + kEPS);
            gy[(size_t)(t0 + t) * D_ + jbase + c] = num * inv;
        }
    }
}

// ---------------------------------------------------------------------------
// Launch
// ---------------------------------------------------------------------------
extern "C" void kernel_launch(void* const* d_in, const int* in_sizes, int n_in,
                              void* d_out, int out_size)
{
    const float* x  = (const float*)d_in[0];
    const float* Wq = (const float*)d_in[1];
    const float* bq = (const float*)d_in[2];
    const float* Wk = (const float*)d_in[3];
    const float* bk = (const float*)d_in[4];
    const float* Wv = (const float*)d_in[5];
    const float* bv = (const float*)d_in[6];
    const float* Wa = (const float*)d_in[7];
    const float* ba = (const float*)d_in[8];
    float* y = (float*)d_out;

    dim3 ggrid(D_ / 128, (B_ * S_) / 128, 4);
    proj_gemm_kernel<<<ggrid, 256>>>(x, Wq, bq, Wk, bk, Wv, bv, Wa, ba);

    cudaFuncSetAttribute(scan_chunk_kernel,
                         cudaFuncAttributeMaxDynamicSharedMemorySize,
                         SCAN_SMEM_BYTES);
    dim3 sgrid(D_ / 32, B_);
    scan_chunk_kernel<<<sgrid, 512, SCAN_SMEM_BYTES>>>(y);
}

// round 6
// speedup vs baseline: 1.4376x; 1.2773x over previous
#include <cuda_runtime.h>
#include <cuda_bf16.h>
#include <cstdint>
#include <cstddef>

// Problem constants
#define B_ 8
#define S_ 4096
#define D_ 512
#define C_ 16                 // chunk length
#define NCH_ (S_ / C_)        // 256 chunks
#define M_TOT (B_ * S_)       // 32768

static __device__ __constant__ float kEPS = 1e-6f;

// ---------------------------------------------------------------------------
// Scratch (device globals: no allocation allowed)
// ---------------------------------------------------------------------------
__device__ float g_q[(size_t)B_ * S_ * D_];
__device__ float g_k[(size_t)B_ * S_ * D_];
__device__ float g_v[(size_t)B_ * S_ * D_];
__device__ float g_a[(size_t)B_ * S_ * D_];

// bf16 hi/lo split operands for tensor-core projections
__device__ __nv_bfloat16 g_xhi[(size_t)M_TOT * D_];
__device__ __nv_bfloat16 g_xlo[(size_t)M_TOT * D_];
__device__ __nv_bfloat16 g_whi[4 * D_ * D_];
__device__ __nv_bfloat16 g_wlo[4 * D_ * D_];

// ---------------------------------------------------------------------------
// f32x2 packed-math helpers (scan)
// ---------------------------------------------------------------------------
typedef unsigned long long u64;

__device__ __forceinline__ u64 pack2(float lo, float hi) {
    u64 r;
    asm("mov.b64 %0, {%1, %2};" : "=l"(r) : "f"(lo), "f"(hi));
    return r;
}
__device__ __forceinline__ void unpack2(u64 v, float& lo, float& hi) {
    asm("mov.b64 {%0, %1}, %2;" : "=f"(lo), "=f"(hi) : "l"(v));
}
__device__ __forceinline__ u64 fma2(u64 a, u64 b, u64 c) {
    u64 d;
    asm("fma.rn.f32x2 %0, %1, %2, %3;" : "=l"(d) : "l"(a), "l"(b), "l"(c));
    return d;
}
__device__ __forceinline__ u64 mul2(u64 a, u64 b) {
    u64 d;
    asm("mul.rn.f32x2 %0, %1, %2;" : "=l"(d) : "l"(a), "l"(b));
    return d;
}

// ---------------------------------------------------------------------------
// Tensor-core helpers
// ---------------------------------------------------------------------------
__device__ __forceinline__ uint32_t smem_u32(const void* p) {
    uint32_t a;
    asm("{ .reg .u64 t; cvta.to.shared.u64 t, %1; cvt.u32.u64 %0, t; }"
        : "=r"(a) : "l"(p));
    return a;
}
__device__ __forceinline__ void ldsm4(uint32_t* r, uint32_t addr) {
    asm volatile("ldmatrix.sync.aligned.m8n8.x4.shared.b16 {%0,%1,%2,%3}, [%4];"
                 : "=r"(r[0]), "=r"(r[1]), "=r"(r[2]), "=r"(r[3]) : "r"(addr));
}
__device__ __forceinline__ void mma16816(float* c, const uint32_t* a,
                                         uint32_t b0, uint32_t b1) {
    asm volatile(
        "mma.sync.aligned.m16n8k16.row.col.f32.bf16.bf16.f32 "
        "{%0,%1,%2,%3}, {%4,%5,%6,%7}, {%8,%9}, {%0,%1,%2,%3};"
        : "+f"(c[0]), "+f"(c[1]), "+f"(c[2]), "+f"(c[3])
        : "r"(a[0]), "r"(a[1]), "r"(a[2]), "r"(a[3]), "r"(b0), "r"(b1));
}
__device__ __forceinline__ void cp16(uint32_t saddr, const void* g) {
    asm volatile("cp.async.cg.shared.global [%0], [%1], 16;"
                 :: "r"(saddr), "l"(g));
}

__device__ __forceinline__ float act_apply(float x, int act) {
    if (act == 1) return fmaxf(x, 0.0f);               // relu
    if (act == 2) return 1.0f / (1.0f + __expf(-x));   // sigmoid
    return x;
}

// ---------------------------------------------------------------------------
// fp32 -> bf16 hi/lo split (x = hi + lo to ~2^-16 rel)
// ---------------------------------------------------------------------------
__global__ void __launch_bounds__(256) convert_split_kernel(
    const float* __restrict__ src,
    __nv_bfloat16* __restrict__ hi,
    __nv_bfloat16* __restrict__ lo, int n2)
{
    const int idx = blockIdx.x * blockDim.x + threadIdx.x;
    const int stride = gridDim.x * blockDim.x;
    const float2* s2 = (const float2*)src;
    __nv_bfloat162* h2 = (__nv_bfloat162*)hi;
    __nv_bfloat162* l2 = (__nv_bfloat162*)lo;
    for (int i = idx; i < n2; i += stride) {
        const float2 x = s2[i];
        const __nv_bfloat16 h0 = __float2bfloat16(x.x);
        const __nv_bfloat16 h1 = __float2bfloat16(x.y);
        __nv_bfloat162 hh; hh.x = h0; hh.y = h1;
        __nv_bfloat162 ll;
        ll.x = __float2bfloat16(x.x - __bfloat162float(h0));
        ll.y = __float2bfloat16(x.y - __bfloat162float(h1));
        h2[i] = hh;
        l2[i] = ll;
    }
}

// ---------------------------------------------------------------------------
// Tensor-core projection GEMM: out[m,e] = act( X[m,:] . W[e,:] + b[e] )
//   3-pass bf16: Xhi*Whi + Xhi*Wlo + Xlo*Whi, fp32 accumulate.
//   CTA tile 128(m) x 128(n), k-chunk 32, cp.async double buffer.
//   8 warps: (wm 0..1) x (wn 0..3); warp tile 64x32; 16 m16n8 accum tiles.
// ---------------------------------------------------------------------------
#define GK 32                       // k per chunk
#define NKCH (D_ / GK)              // 16 chunks
#define ROWB 80                     // smem row stride bytes (40 bf16)
#define TILEB (128 * ROWB)          // 10240 B per matrix
#define ABUF_HI 0
#define ABUF_LO TILEB
#define BBUF_HI (2 * TILEB)
#define BBUF_LO (3 * TILEB)
#define BUFB (4 * TILEB)            // 40960 B per stage
#define GEMM_SMEM (2 * BUFB)        // 80 KB

__global__ void __launch_bounds__(256, 1) proj_mma_kernel(
    const float* __restrict__ bq, const float* __restrict__ bk,
    const float* __restrict__ bv, const float* __restrict__ ba)
{
    extern __shared__ __align__(16) char smem[];
    const uint32_t sbase = smem_u32(smem);

    const int pz = blockIdx.z;
    const float* bias;
    float* out;
    int act;
    if (pz == 0)      { bias = bq; out = g_q; act = 1; }
    else if (pz == 1) { bias = bk; out = g_k; act = 1; }
    else if (pz == 2) { bias = bv; out = g_v; act = 0; }
    else              { bias = ba; out = g_a; act = 2; }

    const int tid = threadIdx.x;
    const int w = tid >> 5;
    const int l = tid & 31;
    const int wm = w >> 2;          // 0..1
    const int wn = w & 3;           // 0..3

    const int mBase = blockIdx.y * 128;
    const int nBase = blockIdx.x * 128;

    const __nv_bfloat16* Whi = g_whi + (size_t)pz * D_ * D_;
    const __nv_bfloat16* Wlo = g_wlo + (size_t)pz * D_ * D_;

    // per-thread load slots: 2 x (row, seg)
    const int slot0 = tid;            // rows 0..63, via slot>>2
    const int slot1 = tid + 256;
    const int r0s = slot0 >> 2, s0s = slot0 & 3;
    const int r1s = slot1 >> 2, s1s = slot1 & 3;

    auto load_chunk = [&](int buf, int kc) {
        const uint32_t sb = sbase + buf * BUFB;
        const int k0 = kc * GK;
        {
            const size_t ga = (size_t)(mBase + r0s) * D_ + k0 + s0s * 8;
            const size_t gb = (size_t)(nBase + r0s) * D_ + k0 + s0s * 8;
            const uint32_t so = r0s * ROWB + s0s * 16;
            cp16(sb + ABUF_HI + so, g_xhi + ga);
            cp16(sb + ABUF_LO + so, g_xlo + ga);
            cp16(sb + BBUF_HI + so, Whi + gb);
            cp16(sb + BBUF_LO + so, Wlo + gb);
        }
        {
            const size_t ga = (size_t)(mBase + r1s) * D_ + k0 + s1s * 8;
            const size_t gb = (size_t)(nBase + r1s) * D_ + k0 + s1s * 8;
            const uint32_t so = r1s * ROWB + s1s * 16;
            cp16(sb + ABUF_HI + so, g_xhi + ga);
            cp16(sb + ABUF_LO + so, g_xlo + ga);
            cp16(sb + BBUF_HI + so, Whi + gb);
            cp16(sb + BBUF_LO + so, Wlo + gb);
        }
        asm volatile("cp.async.commit_group;");
    };

    float acc[4][4][4];
#pragma unroll
    for (int i = 0; i < 4; ++i)
#pragma unroll
        for (int j = 0; j < 4; ++j)
#pragma unroll
            for (int e = 0; e < 4; ++e) acc[i][j][e] = 0.0f;

    // ldmatrix lane address components
    const int lrow = l & 15;
    const int lcol16 = (l >> 4) & 1;    // 0/1 -> +16B

    load_chunk(0, 0);

#pragma unroll 1
    for (int kc = 0; kc < NKCH; ++kc) {
        const int buf = kc & 1;
        if (kc + 1 < NKCH) {
            load_chunk(buf ^ 1, kc + 1);
            asm volatile("cp.async.wait_group 1;");
        } else {
            asm volatile("cp.async.wait_group 0;");
        }
        __syncthreads();

        const uint32_t sb = sbase + buf * BUFB;
#pragma unroll
        for (int kh = 0; kh < 2; ++kh) {       // two k16 halves of the k32 chunk
            const uint32_t coff = kh * 32 + lcol16 * 16;
            uint32_t ah[4][4], al[4][4];
#pragma unroll
            for (int mt = 0; mt < 4; ++mt) {
                const uint32_t ra = (wm * 64 + mt * 16 + lrow) * ROWB + coff;
                ldsm4(ah[mt], sb + ABUF_HI + ra);
                ldsm4(al[mt], sb + ABUF_LO + ra);
            }
            uint32_t bh[2][4], bl[2][4];
#pragma unroll
            for (int bt = 0; bt < 2; ++bt) {
                const uint32_t rb = (wn * 32 + bt * 16 + lrow) * ROWB + coff;
                ldsm4(bh[bt], sb + BBUF_HI + rb);
                ldsm4(bl[bt], sb + BBUF_LO + rb);
            }
#pragma unroll
            for (int mt = 0; mt < 4; ++mt)
#pragma unroll
                for (int nt = 0; nt < 4; ++nt) {
                    const int bt = nt >> 1;
                    const int hf = nt & 1;
                    mma16816(acc[mt][nt], ah[mt], bh[bt][hf], bh[bt][hf + 2]);
                    mma16816(acc[mt][nt], ah[mt], bl[bt][hf], bl[bt][hf + 2]);
                    mma16816(acc[mt][nt], al[mt], bh[bt][hf], bh[bt][hf + 2]);
                }
        }
        __syncthreads();
    }

    // Epilogue: bias + activation + store fp32
#pragma unroll
    for (int nt = 0; nt < 4; ++nt) {
        const int col = nBase + wn * 32 + nt * 8 + 2 * (l & 3);
        const float2 b2 = *(const float2*)(bias + col);
#pragma unroll
        for (int mt = 0; mt < 4; ++mt) {
            const int row = mBase + wm * 64 + mt * 16 + (l >> 2);
            float2 r0, r1;
            r0.x = act_apply(acc[mt][nt][0] + b2.x, act);
            r0.y = act_apply(acc[mt][nt][1] + b2.y, act);
            r1.x = act_apply(acc[mt][nt][2] + b2.x, act);
            r1.y = act_apply(acc[mt][nt][3] + b2.y, act);
            *(float2*)(out + (size_t)row * D_ + col) = r0;
            *(float2*)(out + (size_t)(row + 8) * D_ + col) = r1;
        }
    }
}

// ---------------------------------------------------------------------------
// Chunked scan (unchanged from round 5)
// ---------------------------------------------------------------------------
#define SM_QTP  0
#define SM_KTP  (SM_QTP + 256*36)
#define SM_ACP  (SM_KTP + 256*36)
#define SM_V    (SM_ACP + 512)
#define SM_PART (SM_V + 512)
#define SM_DEN  (SM_PART + 16*32*17)
#define SM_FLOATS (SM_DEN + 512*17)
#define SCAN_SMEM_BYTES (SM_FLOATS * 4)

__global__ void __launch_bounds__(512, 1) scan_chunk_kernel(float* __restrict__ y)
{
    extern __shared__ __align__(16) float sm[];
    float* sQtp = sm + SM_QTP;
    float* sKtp = sm + SM_KTP;
    float* sACp = sm + SM_ACP;
    float* sV   = sm + SM_V;
    float* sPart= sm + SM_PART;
    float* sDen = sm + SM_DEN;

    const int b = blockIdx.y;
    const int jbase = blockIdx.x * 32;
    const int tid = threadIdx.x;
    const int w = tid >> 5;
    const int c = tid & 31;

    const float* gq = g_q + (size_t)b * S_ * D_;
    const float* gk = g_k + (size_t)b * S_ * D_;
    const float* gv = g_v + (size_t)b * S_ * D_;
    const float* ga = g_a + (size_t)b * S_ * D_;
    float* gy = y + (size_t)b * S_ * D_;

    u64 su[16];
#pragma unroll
    for (int pp = 0; pp < 16; ++pp) su[pp] = 0ull;
    float zreg = 0.0f;

    const int i_ = tid;
    const int p_ = i_ >> 1;
    const int hv_ = i_ & 1;

    {
        const int tpf = c & 15;
        const size_t roff = (size_t)tpf * D_ + w * 32;
        if (c < 16) {
            asm volatile("prefetch.global.L2 [%0];" :: "l"(gq + roff));
            asm volatile("prefetch.global.L2 [%0];" :: "l"(ga + roff));
        } else {
            asm volatile("prefetch.global.L2 [%0];" :: "l"(gk + roff));
            if (w == 0)
                asm volatile("prefetch.global.L2 [%0];"
                             :: "l"(gv + (size_t)tpf * D_ + jbase));
        }
    }

#pragma unroll 1
    for (int ch = 0; ch < NCH_; ++ch) {
        const int t0 = ch * C_;

        __syncthreads();   // B0

        {
            float av[16], qv[16], kv[16];
#pragma unroll
            for (int t = 0; t < 16; ++t) av[t] = ga[(size_t)(t0 + t) * D_ + i_];
#pragma unroll
            for (int t = 0; t < 16; ++t) qv[t] = gq[(size_t)(t0 + t) * D_ + i_];
#pragma unroll
            for (int t = 0; t < 16; ++t) kv[t] = gk[(size_t)(t0 + t) * D_ + i_];

            float A[16], invA[16];
            A[0] = av[0];
#pragma unroll
            for (int t = 1; t < 16; ++t) A[t] = A[t - 1] * av[t];
            invA[15] = __frcp_rn(A[15]);
#pragma unroll
            for (int t = 15; t >= 1; --t) invA[t - 1] = invA[t] * av[t];

            float zu = zreg;
#pragma unroll
            for (int t = 0; t < 16; ++t) {
                const float qt = qv[t] * A[t];
                const float kt = kv[t] * invA[t];
                zu += kt;
                sDen[i_ * 17 + t] = qt * zu;
                sQtp[p_ * 36 + t * 2 + hv_] = qt;
                sKtp[p_ * 36 + t * 2 + hv_] = kt;
            }
            zreg = A[15] * zu;
            sACp[p_ * 2 + hv_] = A[15];
        }

        if (tid < 128) {
            const int tv = tid >> 3;
            const int c4 = (tid & 7) << 2;
            const float4 vv = *(const float4*)(gv + (size_t)(t0 + tv) * D_ + jbase + c4);
            *(float4*)&sV[tv * 32 + c4] = vv;
        }

        __syncthreads();   // B1

        if (ch + 1 < NCH_) {
            const int tpf = c & 15;
            const size_t roff = (size_t)(t0 + 16 + tpf) * D_ + w * 32;
            if (c < 16) {
                asm volatile("prefetch.global.L2 [%0];" :: "l"(gq + roff));
                asm volatile("prefetch.global.L2 [%0];" :: "l"(ga + roff));
            } else {
                asm volatile("prefetch.global.L2 [%0];" :: "l"(gk + roff));
                if (w == 0)
                    asm volatile("prefetch.global.L2 [%0];"
                                 :: "l"(gv + (size_t)(t0 + 16 + tpf) * D_ + jbase));
            }
        }

#pragma unroll
        for (int th = 0; th < 2; ++th) {
            u64 vd[8];
#pragma unroll
            for (int tt = 0; tt < 8; ++tt) {
                const float vv = sV[(th * 8 + tt) * 32 + c];
                vd[tt] = pack2(vv, vv);
            }
            u64 nacc[8];
#pragma unroll
            for (int tt = 0; tt < 8; ++tt) nacc[tt] = 0ull;

#pragma unroll 4
            for (int pp = 0; pp < 16; ++pp) {
                const int p = w * 16 + pp;
                const ulonglong2* kr = (const ulonglong2*)(sKtp + p * 36 + th * 16);
                const ulonglong2* qr = (const ulonglong2*)(sQtp + p * 36 + th * 16);
                const ulonglong2 k01 = kr[0], k23 = kr[1], k45 = kr[2], k67 = kr[3];
                const ulonglong2 q01 = qr[0], q23 = qr[1], q45 = qr[2], q67 = qr[3];
                u64 s = su[pp];
                s = fma2(k01.x, vd[0], s); nacc[0] = fma2(q01.x, s, nacc[0]);
                s = fma2(k01.y, vd[1], s); nacc[1] = fma2(q01.y, s, nacc[1]);
                s = fma2(k23.x, vd[2], s); nacc[2] = fma2(q23.x, s, nacc[2]);
                s = fma2(k23.y, vd[3], s); nacc[3] = fma2(q23.y, s, nacc[3]);
                s = fma2(k45.x, vd[4], s); nacc[4] = fma2(q45.x, s, nacc[4]);
                s = fma2(k45.y, vd[5], s); nacc[5] = fma2(q45.y, s, nacc[5]);
                s = fma2(k67.x, vd[6], s); nacc[6] = fma2(q67.x, s, nacc[6]);
                s = fma2(k67.y, vd[7], s); nacc[7] = fma2(q67.y, s, nacc[7]);
                su[pp] = s;
            }

#pragma unroll
            for (int tt = 0; tt < 8; ++tt) {
                float lo, hi;
                unpack2(nacc[tt], lo, hi);
                sPart[((th * 8 + tt) * 32 + c) * 17 + w] = lo + hi;
            }
        }

#pragma unroll
        for (int pp = 0; pp < 16; ++pp) {
            const u64 acp = *(const u64*)(sACp + (w * 16 + pp) * 2);
            su[pp] = mul2(su[pp], acp);
        }

        __syncthreads();   // B2

        {
            const int t = w;
            float num = 0.0f;
            float dpart = 0.0f;
#pragma unroll
            for (int ww = 0; ww < 16; ++ww) {
                num   += sPart[(t * 32 + c) * 17 + ww];
                dpart += sDen[(ww * 32 + c) * 17 + t];
            }
#pragma unroll
            for (int off = 16; off; off >>= 1)
                dpart += __shfl_xor_sync(0xffffffffu, dpart, off);
            const float inv = 1.0f / (dpart + kEPS);
            gy[(size_t)(t0 + t) * D_ + jbase + c] = num * inv;
        }
    }
}

// ---------------------------------------------------------------------------
// Launch
// ---------------------------------------------------------------------------
extern "C" void kernel_launch(void* const* d_in, const int* in_sizes, int n_in,
                              void* d_out, int out_size)
{
    const float* x  = (const float*)d_in[0];
    const float* Wq = (const float*)d_in[1];
    const float* bq = (const float*)d_in[2];
    const float* Wk = (const float*)d_in[3];
    const float* bk = (const float*)d_in[4];
    const float* Wv = (const float*)d_in[5];
    const float* bv = (const float*)d_in[6];
    const float* Wa = (const float*)d_in[7];
    const float* ba = (const float*)d_in[8];
    float* y = (float*)d_out;

    // Resolve device-global scratch addresses (host side, capture-safe)
    static __nv_bfloat16 *p_xhi = nullptr, *p_xlo = nullptr,
                         *p_whi = nullptr, *p_wlo = nullptr;
    if (!p_xhi) {
        cudaGetSymbolAddress((void**)&p_xhi, g_xhi);
        cudaGetSymbolAddress((void**)&p_xlo, g_xlo);
        cudaGetSymbolAddress((void**)&p_whi, g_whi);
        cudaGetSymbolAddress((void**)&p_wlo, g_wlo);
    }

    // 1) fp32 -> bf16 hi/lo splits
    convert_split_kernel<<<2048, 256>>>(x, p_xhi, p_xlo, (M_TOT * D_) / 2);
    convert_split_kernel<<<64, 256>>>(Wq, p_whi + 0 * D_ * D_, p_wlo + 0 * D_ * D_, (D_ * D_) / 2);
    convert_split_kernel<<<64, 256>>>(Wk, p_whi + 1 * D_ * D_, p_wlo + 1 * D_ * D_, (D_ * D_) / 2);
    convert_split_kernel<<<64, 256>>>(Wv, p_whi + 2 * D_ * D_, p_wlo + 2 * D_ * D_, (D_ * D_) / 2);
    convert_split_kernel<<<64, 256>>>(Wa, p_whi + 3 * D_ * D_, p_wlo + 3 * D_ * D_, (D_ * D_) / 2);

    // 2) tensor-core projections
    cudaFuncSetAttribute(proj_mma_kernel,
                         cudaFuncAttributeMaxDynamicSharedMemorySize, GEMM_SMEM);
    dim3 ggrid(D_ / 128, M_TOT / 128, 4);
    proj_mma_kernel<<<ggrid, 256, GEMM_SMEM>>>(bq, bk, bv, ba);

    // 3) chunked scan
    cudaFuncSetAttribute(scan_chunk_kernel,
                         cudaFuncAttributeMaxDynamicSharedMemorySize,
                         SCAN_SMEM_BYTES);
    dim3 sgrid(D_ / 32, B_);
    scan_chunk_kernel<<<sgrid, 512, SCAN_SMEM_BYTES>>>(y);
}